// round 2
// baseline (speedup 1.0000x reference)
#include <cuda_runtime.h>
#include <math.h>

#define B_    64
#define T_    128
#define IN_   64
#define TE_   256
#define H_    512
#define A_    256
#define OUT_  64
#define G4_   2048          // 4*H
#define KIN_  1088          // IN + H(context) + H(h)

// persistent scratch (static device globals; no runtime allocation)
__device__ float g_keys[B_ * TE_ * A_];     // 16.8 MB
__device__ float g_inp [B_ * KIN_];         // [x | context | h]
__device__ float g_c   [B_ * H_];
__device__ float g_part[4 * B_ * G4_];      // k-split partial gate sums
__device__ float g_hist[B_ * T_ * H_];      // h history for deferred FC

__device__ __forceinline__ float sigf(float xx) {
    return 1.0f / (1.0f + __expf(-xx));
}
__device__ __forceinline__ float tanh_fast(float xx) {
    xx = fminf(fmaxf(xx, -15.f), 15.f);
    float e2 = __expf(2.f * xx);
    return __fdividef(e2 - 1.f, e2 + 1.f);
}

__device__ __forceinline__ float blk_reduce_max(float vv, float* red) {
#pragma unroll
    for (int o = 16; o > 0; o >>= 1)
        vv = fmaxf(vv, __shfl_xor_sync(0xffffffffu, vv, o));
    if ((threadIdx.x & 31) == 0) red[threadIdx.x >> 5] = vv;
    __syncthreads();
    if (threadIdx.x == 0) {
        float mm = red[0];
#pragma unroll
        for (int i = 1; i < 8; i++) mm = fmaxf(mm, red[i]);
        red[0] = mm;
    }
    __syncthreads();
    float r = red[0];
    __syncthreads();
    return r;
}
__device__ __forceinline__ float blk_reduce_sum(float vv, float* red) {
#pragma unroll
    for (int o = 16; o > 0; o >>= 1)
        vv += __shfl_xor_sync(0xffffffffu, vv, o);
    if ((threadIdx.x & 31) == 0) red[threadIdx.x >> 5] = vv;
    __syncthreads();
    if (threadIdx.x == 0) {
        float ss = red[0];
#pragma unroll
        for (int i = 1; i < 8; i++) ss += red[i];
        red[0] = ss;
    }
    __syncthreads();
    float r = red[0];
    __syncthreads();
    return r;
}

// ---------------------------------------------------------------------------
// Generic C[M,N] = A[M,K] * B[N,K]^T (+ bias[N]); M,N multiples of 64, K of 16
// 256 threads, CTA tile 64x64, thread tile 4x4, double-buffered SMEM.
// ---------------------------------------------------------------------------
__global__ void __launch_bounds__(256) gemm_abt_kernel(
    const float* __restrict__ Am, const float* __restrict__ Bm,
    float* __restrict__ Cm, int M, int N, int K, const float* __restrict__ bias)
{
    __shared__ float As[2][16][68];
    __shared__ float Bs[2][16][68];
    const int m0 = blockIdx.x * 64, n0 = blockIdx.y * 64;
    const int tid  = threadIdx.x;
    const int lrow = tid >> 2, lk = (tid & 3) << 2;
    const int tm   = (tid & 15) << 2, tn = (tid >> 4) << 2;
    const float* Ag = Am + (size_t)(m0 + lrow) * K + lk;
    const float* Bg = Bm + (size_t)(n0 + lrow) * K + lk;
    const int nc = K >> 4;

    float4 ra = *(const float4*)Ag;
    float4 rb = *(const float4*)Bg;
    float acc[4][4];
#pragma unroll
    for (int i = 0; i < 4; i++)
#pragma unroll
        for (int j = 0; j < 4; j++) acc[i][j] = 0.f;

    int buf = 0;
    As[0][lk + 0][lrow] = ra.x; As[0][lk + 1][lrow] = ra.y;
    As[0][lk + 2][lrow] = ra.z; As[0][lk + 3][lrow] = ra.w;
    Bs[0][lk + 0][lrow] = rb.x; Bs[0][lk + 1][lrow] = rb.y;
    Bs[0][lk + 2][lrow] = rb.z; Bs[0][lk + 3][lrow] = rb.w;
    __syncthreads();

    for (int c = 0; c < nc; c++) {
        if (c + 1 < nc) {
            ra = *(const float4*)(Ag + (c + 1) * 16);
            rb = *(const float4*)(Bg + (c + 1) * 16);
        }
#pragma unroll
        for (int kk = 0; kk < 16; kk++) {
            float4 av = *(const float4*)&As[buf][kk][tm];
            float4 bv = *(const float4*)&Bs[buf][kk][tn];
            acc[0][0] += av.x * bv.x; acc[0][1] += av.x * bv.y;
            acc[0][2] += av.x * bv.z; acc[0][3] += av.x * bv.w;
            acc[1][0] += av.y * bv.x; acc[1][1] += av.y * bv.y;
            acc[1][2] += av.y * bv.z; acc[1][3] += av.y * bv.w;
            acc[2][0] += av.z * bv.x; acc[2][1] += av.z * bv.y;
            acc[2][2] += av.z * bv.z; acc[2][3] += av.z * bv.w;
            acc[3][0] += av.w * bv.x; acc[3][1] += av.w * bv.y;
            acc[3][2] += av.w * bv.z; acc[3][3] += av.w * bv.w;
        }
        __syncthreads();
        if (c + 1 < nc) {
            buf ^= 1;
            As[buf][lk + 0][lrow] = ra.x; As[buf][lk + 1][lrow] = ra.y;
            As[buf][lk + 2][lrow] = ra.z; As[buf][lk + 3][lrow] = ra.w;
            Bs[buf][lk + 0][lrow] = rb.x; Bs[buf][lk + 1][lrow] = rb.y;
            Bs[buf][lk + 2][lrow] = rb.z; Bs[buf][lk + 3][lrow] = rb.w;
            __syncthreads();
        }
    }

    float b0 = 0.f, b1 = 0.f, b2 = 0.f, b3 = 0.f;
    if (bias) {
        b0 = bias[n0 + tn + 0]; b1 = bias[n0 + tn + 1];
        b2 = bias[n0 + tn + 2]; b3 = bias[n0 + tn + 3];
    }
#pragma unroll
    for (int i = 0; i < 4; i++) {
        float4 o;
        o.x = acc[i][0] + b0; o.y = acc[i][1] + b1;
        o.z = acc[i][2] + b2; o.w = acc[i][3] + b3;
        *(float4*)&Cm[(size_t)(m0 + tm + i) * N + n0 + tn] = o;
    }
}

// ---------------------------------------------------------------------------
// Gates GEMM: part[ks][b, n] = sum_{k in split ks} inp[b,k] * W(n,k)
// W(n,k) = W_ih[n,k] for k<576 else W_hh[n,k-576]. grid (32 n-tiles, 4 k-splits)
// ---------------------------------------------------------------------------
__global__ void __launch_bounds__(256) gates_kernel(
    const float* __restrict__ Wih, const float* __restrict__ Whh)
{
    __shared__ float As[2][16][68];
    __shared__ float Bs[2][16][68];
    const int n0 = blockIdx.x * 64;
    const int ks = blockIdx.y;
    const int kbase = ks * 272;              // 1088/4, multiple of 16
    const int tid  = threadIdx.x;
    const int lrow = tid >> 2, lk = (tid & 3) << 2;
    const int tm   = (tid & 15) << 2, tn = (tid >> 4) << 2;
    const float* Ag = g_inp + lrow * KIN_ + kbase + lk;
    const int nrow  = n0 + lrow;
    const int nc = 17;

    float4 ra = *(const float4*)Ag;
    int gk0 = kbase + lk;
    const float* bp0 = (gk0 < 576) ? (Wih + (size_t)nrow * 576 + gk0)
                                   : (Whh + (size_t)nrow * 512 + (gk0 - 576));
    float4 rb = *(const float4*)bp0;

    float acc[4][4];
#pragma unroll
    for (int i = 0; i < 4; i++)
#pragma unroll
        for (int j = 0; j < 4; j++) acc[i][j] = 0.f;

    int buf = 0;
    As[0][lk + 0][lrow] = ra.x; As[0][lk + 1][lrow] = ra.y;
    As[0][lk + 2][lrow] = ra.z; As[0][lk + 3][lrow] = ra.w;
    Bs[0][lk + 0][lrow] = rb.x; Bs[0][lk + 1][lrow] = rb.y;
    Bs[0][lk + 2][lrow] = rb.z; Bs[0][lk + 3][lrow] = rb.w;
    __syncthreads();

    for (int c = 0; c < nc; c++) {
        if (c + 1 < nc) {
            ra = *(const float4*)(Ag + (c + 1) * 16);
            int gk = kbase + (c + 1) * 16 + lk;
            const float* bp = (gk < 576) ? (Wih + (size_t)nrow * 576 + gk)
                                         : (Whh + (size_t)nrow * 512 + (gk - 576));
            rb = *(const float4*)bp;
        }
#pragma unroll
        for (int kk = 0; kk < 16; kk++) {
            float4 av = *(const float4*)&As[buf][kk][tm];
            float4 bv = *(const float4*)&Bs[buf][kk][tn];
            acc[0][0] += av.x * bv.x; acc[0][1] += av.x * bv.y;
            acc[0][2] += av.x * bv.z; acc[0][3] += av.x * bv.w;
            acc[1][0] += av.y * bv.x; acc[1][1] += av.y * bv.y;
            acc[1][2] += av.y * bv.z; acc[1][3] += av.y * bv.w;
            acc[2][0] += av.z * bv.x; acc[2][1] += av.z * bv.y;
            acc[2][2] += av.z * bv.z; acc[2][3] += av.z * bv.w;
            acc[3][0] += av.w * bv.x; acc[3][1] += av.w * bv.y;
            acc[3][2] += av.w * bv.z; acc[3][3] += av.w * bv.w;
        }
        __syncthreads();
        if (c + 1 < nc) {
            buf ^= 1;
            As[buf][lk + 0][lrow] = ra.x; As[buf][lk + 1][lrow] = ra.y;
            As[buf][lk + 2][lrow] = ra.z; As[buf][lk + 3][lrow] = ra.w;
            Bs[buf][lk + 0][lrow] = rb.x; Bs[buf][lk + 1][lrow] = rb.y;
            Bs[buf][lk + 2][lrow] = rb.z; Bs[buf][lk + 3][lrow] = rb.w;
            __syncthreads();
        }
    }

    float* Cp = g_part + (size_t)ks * (B_ * G4_);
#pragma unroll
    for (int i = 0; i < 4; i++) {
        float4 o;
        o.x = acc[i][0]; o.y = acc[i][1]; o.z = acc[i][2]; o.w = acc[i][3];
        *(float4*)&Cp[(size_t)(tm + i) * G4_ + n0 + tn] = o;
    }
}

// ---------------------------------------------------------------------------
// Per-step kernel: one CTA per batch element.
// Phase A: combine gate partials of previous step -> LSTM update -> h
// Phase B: q = h @ Wq^T       Phase C: energies + softmax
// Phase D: context = w @ enc  (written into g_inp for the gates GEMM)
// ---------------------------------------------------------------------------
__global__ void __launch_bounds__(256) step_kernel(
    const float* __restrict__ x, const float* __restrict__ enc,
    const float* __restrict__ Wq, const float* __restrict__ v,
    const float* __restrict__ bih, const float* __restrict__ bhh,
    int t, int do_attn)
{
    __shared__ float h_s[H_];
    __shared__ float q_s[A_];
    __shared__ float w_s[TE_];
    __shared__ float v_s[A_];
    __shared__ float red[8];
    const int b = blockIdx.x, tid = threadIdx.x;

    if (t == 0) {
        for (int u = tid; u < H_; u += 256) {
            h_s[u] = 0.f;
            g_c[b * H_ + u] = 0.f;
            g_inp[b * KIN_ + 576 + u] = 0.f;
        }
    } else {
        for (int u = tid; u < H_; u += 256) {
            float gi = bih[u]          + bhh[u];
            float gf = bih[H_ + u]     + bhh[H_ + u];
            float gg = bih[2 * H_ + u] + bhh[2 * H_ + u];
            float go = bih[3 * H_ + u] + bhh[3 * H_ + u];
#pragma unroll
            for (int p = 0; p < 4; p++) {
                const float* pp = g_part + (size_t)p * (B_ * G4_) + b * G4_;
                gi += pp[u]; gf += pp[H_ + u]; gg += pp[2 * H_ + u]; go += pp[3 * H_ + u];
            }
            float co = g_c[b * H_ + u];
            float cn = sigf(gf) * co + sigf(gi) * tanhf(gg);
            float hn = sigf(go) * tanhf(cn);
            g_c[b * H_ + u] = cn;
            h_s[u] = hn;
            g_inp[b * KIN_ + 576 + u] = hn;
            g_hist[((size_t)b * T_ + (t - 1)) * H_ + u] = hn;  // h after step t-1
        }
    }
    if (do_attn) {
        if (tid < IN_) g_inp[b * KIN_ + tid] = x[((size_t)b * T_ + t) * IN_ + tid];
        v_s[tid] = v[tid];
    }
    __syncthreads();
    if (!do_attn) return;

    // Phase B: q[a] for a = tid (k = 512)
    {
        float a0 = 0.f, a1 = 0.f, a2 = 0.f, a3 = 0.f;
        const float4* wq = (const float4*)(Wq + (size_t)tid * H_);
#pragma unroll 4
        for (int k = 0; k < H_ / 4; k += 4) {
            float4 w0 = wq[k + 0], w1 = wq[k + 1], w2 = wq[k + 2], w3 = wq[k + 3];
            const float* hh = &h_s[4 * k];
            a0 += w0.x * hh[0]  + w0.y * hh[1]  + w0.z * hh[2]  + w0.w * hh[3];
            a1 += w1.x * hh[4]  + w1.y * hh[5]  + w1.z * hh[6]  + w1.w * hh[7];
            a2 += w2.x * hh[8]  + w2.y * hh[9]  + w2.z * hh[10] + w2.w * hh[11];
            a3 += w3.x * hh[12] + w3.y * hh[13] + w3.z * hh[14] + w3.w * hh[15];
        }
        q_s[tid] = (a0 + a1) + (a2 + a3);
    }
    __syncthreads();

    // Phase C: e[t'] for t' = tid, then softmax
    float e;
    {
        float a0 = 0.f, a1 = 0.f;
        const float4* kp = (const float4*)(g_keys + ((size_t)b * TE_ + tid) * A_);
#pragma unroll 4
        for (int a4 = 0; a4 < A_ / 4; a4 += 2) {
            float4 k0 = kp[a4], k1 = kp[a4 + 1];
            int a = 4 * a4;
            a0 += v_s[a + 0] * tanh_fast(q_s[a + 0] + k0.x)
                + v_s[a + 1] * tanh_fast(q_s[a + 1] + k0.y)
                + v_s[a + 2] * tanh_fast(q_s[a + 2] + k0.z)
                + v_s[a + 3] * tanh_fast(q_s[a + 3] + k0.w);
            a1 += v_s[a + 4] * tanh_fast(q_s[a + 4] + k1.x)
                + v_s[a + 5] * tanh_fast(q_s[a + 5] + k1.y)
                + v_s[a + 6] * tanh_fast(q_s[a + 6] + k1.z)
                + v_s[a + 7] * tanh_fast(q_s[a + 7] + k1.w);
        }
        e = a0 + a1;
    }
    float mx = blk_reduce_max(e, red);
    float wv = __expf(e - mx);
    float sm = blk_reduce_sum(wv, red);
    w_s[tid] = wv * __fdividef(1.f, sm);
    __syncthreads();

    // Phase D: context[d] for d = tid, tid+256 (coalesced over enc rows)
    {
        float c0 = 0.f, c1 = 0.f;
        const float* eb = enc + (size_t)b * TE_ * H_;
#pragma unroll 4
        for (int e2 = 0; e2 < TE_; e2++) {
            float ww = w_s[e2];
            const float* er = eb + (size_t)e2 * H_;
            c0 += ww * er[tid];
            c1 += ww * er[tid + 256];
        }
        g_inp[b * KIN_ + IN_ + tid]       = c0;
        g_inp[b * KIN_ + IN_ + 256 + tid] = c1;
    }
}

// ---------------------------------------------------------------------------
extern "C" void kernel_launch(void* const* d_in, const int* in_sizes, int n_in,
                              void* d_out, int out_size)
{
    const float* x   = (const float*)d_in[0];
    const float* enc = (const float*)d_in[1];
    const float* Wq  = (const float*)d_in[2];
    const float* Wk  = (const float*)d_in[3];
    const float* v   = (const float*)d_in[4];
    const float* Wih = (const float*)d_in[5];
    const float* Whh = (const float*)d_in[6];
    const float* bih = (const float*)d_in[7];
    const float* bhh = (const float*)d_in[8];
    const float* Wfc = (const float*)d_in[9];
    const float* bfc = (const float*)d_in[10];

    float* keys_p = nullptr;
    float* hist_p = nullptr;
    cudaGetSymbolAddress((void**)&keys_p, g_keys);
    cudaGetSymbolAddress((void**)&hist_p, g_hist);

    dim3 thr(256);

    // keys[b,e,a] = enc[b,e,:] . W_key[a,:]   (hoisted, timestep-invariant)
    gemm_abt_kernel<<<dim3((B_ * TE_) / 64, A_ / 64), thr>>>(
        enc, Wk, keys_p, B_ * TE_, A_, H_, nullptr);

    for (int t = 0; t < T_; t++) {
        step_kernel<<<B_, thr>>>(x, enc, Wq, v, bih, bhh, t, 1);
        gates_kernel<<<dim3(G4_ / 64, 4), thr>>>(Wih, Whh);
    }
    // final combine (produces h after step 127, no attention)
    step_kernel<<<B_, thr>>>(x, enc, Wq, v, bih, bhh, T_, 0);

    // deferred output FC over the whole h history: out[b,t,:] = h_hist[b,t,:] @ Wfc^T + bfc
    gemm_abt_kernel<<<dim3((B_ * T_) / 64, OUT_ / 64), thr>>>(
        hist_p, Wfc, (float*)d_out, B_ * T_, OUT_, H_, bfc);
}

// round 4
// speedup vs baseline: 1.5075x; 1.5075x over previous
#include <cuda_runtime.h>
#include <math.h>

#define B_    64
#define T_    128
#define IN_   64
#define TE_   256
#define H_    512
#define A_    256
#define OUT_  64
#define G4_   2048
#define KIN_  1088
#define GRID_ 128

__device__ float g_keys [B_*TE_*A_];
__device__ float g_keysT[B_*A_*TE_];
__device__ float g_Wp  [G4_*KIN_];
__device__ float g_bias[G4_];
__device__ float g_inp [B_*KIN_];
__device__ float g_h   [B_*H_];
__device__ float g_qp  [4*B_*A_];
__device__ float g_part[4*B_*G4_];
__device__ float g_hist[B_*T_*H_];
__device__ unsigned g_bar;

__device__ __forceinline__ float sigf(float xx) {
    return 1.0f / (1.0f + __expf(-xx));
}
__device__ __forceinline__ float tanha(float xx) {
    float y;
    asm("tanh.approx.f32 %0, %1;" : "=f"(y) : "f"(xx));
    return y;
}

__device__ __forceinline__ void gbar(unsigned& ep) {
    ep += GRID_;
    __syncthreads();
    if (threadIdx.x == 0) {
        __threadfence();
        atomicAdd(&g_bar, 1u);
        volatile unsigned* p = &g_bar;
        while (*p < ep) __nanosleep(32);
        __threadfence();
    }
    __syncthreads();
}

__device__ __forceinline__ float blk_reduce_max(float vv, float* red) {
#pragma unroll
    for (int o = 16; o > 0; o >>= 1)
        vv = fmaxf(vv, __shfl_xor_sync(0xffffffffu, vv, o));
    if ((threadIdx.x & 31) == 0) red[threadIdx.x >> 5] = vv;
    __syncthreads();
    if (threadIdx.x == 0) {
        float mm = red[0];
#pragma unroll
        for (int i = 1; i < 8; i++) mm = fmaxf(mm, red[i]);
        red[0] = mm;
    }
    __syncthreads();
    float r = red[0];
    __syncthreads();
    return r;
}
__device__ __forceinline__ float blk_reduce_sum(float vv, float* red) {
#pragma unroll
    for (int o = 16; o > 0; o >>= 1)
        vv += __shfl_xor_sync(0xffffffffu, vv, o);
    if ((threadIdx.x & 31) == 0) red[threadIdx.x >> 5] = vv;
    __syncthreads();
    if (threadIdx.x == 0) {
        float ss = red[0];
#pragma unroll
        for (int i = 1; i < 8; i++) ss += red[i];
        red[0] = ss;
    }
    __syncthreads();
    float r = red[0];
    __syncthreads();
    return r;
}

// 64x64xK tile GEMM: C = A(64,K) * B(64,K)^T, smem double-buffered, 4x4/thread.
// S points to 4352 floats of shared. A loaded with __ldcg when CG (mutable data).
template<bool CG>
__device__ __forceinline__ void tile_gemm64(
    const float* __restrict__ Ag, int lda,
    const float* __restrict__ Bg, int ldb,
    int nc, float* S, float acc[4][4])
{
    float (*As)[16][68] = (float(*)[16][68])S;
    float (*Bs)[16][68] = (float(*)[16][68])(S + 2176);
    const int tid = threadIdx.x;
    const int lrow = tid >> 2, lk = (tid & 3) << 2;
    const int tm = (tid & 15) << 2, tn = (tid >> 4) << 2;
    Ag += (size_t)lrow * lda + lk;
    Bg += (size_t)lrow * ldb + lk;
#pragma unroll
    for (int i = 0; i < 4; i++)
#pragma unroll
        for (int j = 0; j < 4; j++) acc[i][j] = 0.f;

    float4 ra = CG ? __ldcg((const float4*)Ag) : *(const float4*)Ag;
    float4 rb = *(const float4*)Bg;
    int buf = 0;
    As[0][lk + 0][lrow] = ra.x; As[0][lk + 1][lrow] = ra.y;
    As[0][lk + 2][lrow] = ra.z; As[0][lk + 3][lrow] = ra.w;
    Bs[0][lk + 0][lrow] = rb.x; Bs[0][lk + 1][lrow] = rb.y;
    Bs[0][lk + 2][lrow] = rb.z; Bs[0][lk + 3][lrow] = rb.w;
    __syncthreads();

    for (int c = 0; c < nc; c++) {
        if (c + 1 < nc) {
            const float4* ap = (const float4*)(Ag + (c + 1) * 16);
            ra = CG ? __ldcg(ap) : *ap;
            rb = *(const float4*)(Bg + (c + 1) * 16);
        }
#pragma unroll
        for (int kk = 0; kk < 16; kk++) {
            float4 av = *(const float4*)&As[buf][kk][tm];
            float4 bv = *(const float4*)&Bs[buf][kk][tn];
            acc[0][0] += av.x * bv.x; acc[0][1] += av.x * bv.y;
            acc[0][2] += av.x * bv.z; acc[0][3] += av.x * bv.w;
            acc[1][0] += av.y * bv.x; acc[1][1] += av.y * bv.y;
            acc[1][2] += av.y * bv.z; acc[1][3] += av.y * bv.w;
            acc[2][0] += av.z * bv.x; acc[2][1] += av.z * bv.y;
            acc[2][2] += av.z * bv.z; acc[2][3] += av.z * bv.w;
            acc[3][0] += av.w * bv.x; acc[3][1] += av.w * bv.y;
            acc[3][2] += av.w * bv.z; acc[3][3] += av.w * bv.w;
        }
        __syncthreads();
        if (c + 1 < nc) {
            buf ^= 1;
            As[buf][lk + 0][lrow] = ra.x; As[buf][lk + 1][lrow] = ra.y;
            As[buf][lk + 2][lrow] = ra.z; As[buf][lk + 3][lrow] = ra.w;
            Bs[buf][lk + 0][lrow] = rb.x; Bs[buf][lk + 1][lrow] = rb.y;
            Bs[buf][lk + 2][lrow] = rb.z; Bs[buf][lk + 3][lrow] = rb.w;
            __syncthreads();
        }
    }
}

// ---------------- prologue / epilogue kernels ----------------
__global__ void reset_kernel() {
    if (threadIdx.x == 0 && blockIdx.x == 0) g_bar = 0u;
}

__global__ void __launch_bounds__(256) pack_kernel(
    const float* __restrict__ Wih, const float* __restrict__ Whh,
    const float* __restrict__ bih, const float* __restrict__ bhh)
{
    int i = blockIdx.x * 256 + threadIdx.x;
    int s = gridDim.x * 256;
    for (int j = i; j < G4_ * KIN_; j += s) {
        int n = j / KIN_, k = j % KIN_;
        g_Wp[j] = (k < 576) ? Wih[(size_t)n * 576 + k]
                            : Whh[(size_t)n * H_ + (k - 576)];
    }
    for (int j = i; j < G4_; j += s) g_bias[j] = bih[j] + bhh[j];
}

__global__ void transpose_kernel() {
    __shared__ float tile[32][33];
    int b = blockIdx.z;
    int e0 = blockIdx.x * 32, a0 = blockIdx.y * 32;
    const float* src = g_keys + ((size_t)b * TE_ + e0) * A_ + a0;
    for (int r = threadIdx.y; r < 32; r += 8)
        tile[r][threadIdx.x] = src[(size_t)r * A_ + threadIdx.x];
    __syncthreads();
    float* dst = g_keysT + ((size_t)b * A_ + a0) * TE_ + e0;
    for (int r = threadIdx.y; r < 32; r += 8)
        dst[(size_t)r * TE_ + threadIdx.x] = tile[threadIdx.x][r];
}

__global__ void __launch_bounds__(256) gemm_abt_kernel(
    const float* __restrict__ Am, const float* __restrict__ Bm,
    float* __restrict__ Cm, int N, int K, const float* __restrict__ bias)
{
    __shared__ float S[4352];
    float acc[4][4];
    const int m0 = blockIdx.x * 64, n0 = blockIdx.y * 64;
    tile_gemm64<false>(Am + (size_t)m0 * K, K, Bm + (size_t)n0 * K, K, K >> 4, S, acc);
    const int tid = threadIdx.x;
    const int tm = (tid & 15) << 2, tn = (tid >> 4) << 2;
    float b0 = 0.f, b1 = 0.f, b2 = 0.f, b3 = 0.f;
    if (bias) {
        b0 = bias[n0 + tn + 0]; b1 = bias[n0 + tn + 1];
        b2 = bias[n0 + tn + 2]; b3 = bias[n0 + tn + 3];
    }
#pragma unroll
    for (int i = 0; i < 4; i++) {
        float4 o;
        o.x = acc[i][0] + b0; o.y = acc[i][1] + b1;
        o.z = acc[i][2] + b2; o.w = acc[i][3] + b3;
        *(float4*)&Cm[(size_t)(m0 + tm + i) * N + n0 + tn] = o;
    }
}

// ---------------- persistent decoder ----------------
__global__ void __launch_bounds__(256, 1) persist_kernel(
    const float* __restrict__ x, const float* __restrict__ enc,
    const float* __restrict__ Wq, const float* __restrict__ v)
{
    __shared__ float S[4352];
    __shared__ float sq[A_], sv[A_], sw[TE_], sred[8];
    __shared__ float4 sctx[256];
    const int tid = threadIdx.x, bid = blockIdx.x;
    unsigned ep = 0;
    const int b0 = bid >> 1, hf = bid & 1;
    const int u0 = hf * 256 + tid;
    float c_reg = 0.f;

    g_h[b0 * H_ + u0] = 0.f;
    g_inp[b0 * KIN_ + IN_ + H_ + u0] = 0.f;
    if (bid < 64) sv[tid] = v[tid];
    gbar(ep);

    for (int t = 0; t < T_; t++) {
        // P1: q partials (16 CTAs): q[b][a] over k-split of 4
        if (bid < 16) {
            const int nt = bid & 3, ks = bid >> 2;
            float acc[4][4];
            tile_gemm64<true>(g_h + ks * 128, H_,
                              Wq + (size_t)(nt * 64) * H_ + ks * 128, H_, 8, S, acc);
            const int tm = (tid & 15) << 2, tn = (tid >> 4) << 2;
            float* C = g_qp + ks * (B_ * A_);
#pragma unroll
            for (int i = 0; i < 4; i++) {
                float4 o = {acc[i][0], acc[i][1], acc[i][2], acc[i][3]};
                *(float4*)&C[(tm + i) * A_ + nt * 64 + tn] = o;
            }
        }
        gbar(ep);

        // P2: attention, one CTA per b (64 CTAs)
        if (bid < 64) {
            const int b = bid;
            sq[tid] = __ldcg(&g_qp[b * A_ + tid])
                    + __ldcg(&g_qp[B_ * A_ + b * A_ + tid])
                    + __ldcg(&g_qp[2 * B_ * A_ + b * A_ + tid])
                    + __ldcg(&g_qp[3 * B_ * A_ + b * A_ + tid]);
            __syncthreads();
            float e = 0.f;
            const float* kp = g_keysT + ((size_t)b * A_) * TE_ + tid;
#pragma unroll 8
            for (int a = 0; a < A_; a++)
                e += sv[a] * tanha(sq[a] + kp[(size_t)a * TE_]);
            float mx = blk_reduce_max(e, sred);
            float wv = __expf(e - mx);
            float sm = blk_reduce_sum(wv, sred);
            sw[tid] = wv * __fdividef(1.f, sm);
            if (tid < IN_)
                g_inp[b * KIN_ + tid] = x[((size_t)b * T_ + t) * IN_ + tid];
            __syncthreads();
            const int d4 = tid & 127, th = tid >> 7;
            float4 acc = {0.f, 0.f, 0.f, 0.f};
            const float4* ebase = (const float4*)(enc + ((size_t)b * TE_) * H_) + d4;
#pragma unroll 4
            for (int e2 = th * 128; e2 < th * 128 + 128; e2++) {
                float ww = sw[e2];
                float4 ev = ebase[(size_t)e2 * (H_ / 4)];
                acc.x += ww * ev.x; acc.y += ww * ev.y;
                acc.z += ww * ev.z; acc.w += ww * ev.w;
            }
            sctx[tid] = acc;
            __syncthreads();
            if (tid < 128) {
                float4 a0 = sctx[tid], a1 = sctx[128 + tid];
                float4 o = {a0.x + a1.x, a0.y + a1.y, a0.z + a1.z, a0.w + a1.w};
                *(float4*)&g_inp[b * KIN_ + IN_ + tid * 4] = o;
            }
        }
        gbar(ep);

        // P5: gates GEMM partials (all 128 CTAs)
        {
            const int nt = bid >> 2, ks = bid & 3;
            float acc[4][4];
            tile_gemm64<true>(g_inp + ks * 272, KIN_,
                              g_Wp + (size_t)(nt * 64) * KIN_ + ks * 272, KIN_, 17, S, acc);
            const int tm = (tid & 15) << 2, tn = (tid >> 4) << 2;
            float* C = g_part + (size_t)ks * (B_ * G4_);
#pragma unroll
            for (int i = 0; i < 4; i++) {
                float4 o = {acc[i][0], acc[i][1], acc[i][2], acc[i][3]};
                *(float4*)&C[(size_t)(tm + i) * G4_ + nt * 64 + tn] = o;
            }
        }
        gbar(ep);

        // P0: combine partials + LSTM cell; c in registers; unit u0 of batch b0
        {
            float gi = g_bias[u0], gf = g_bias[H_ + u0];
            float gg = g_bias[2 * H_ + u0], go = g_bias[3 * H_ + u0];
#pragma unroll
            for (int p = 0; p < 4; p++) {
                const float* pp = g_part + (size_t)p * (B_ * G4_) + b0 * G4_;
                gi += __ldcg(&pp[u0]);
                gf += __ldcg(&pp[H_ + u0]);
                gg += __ldcg(&pp[2 * H_ + u0]);
                go += __ldcg(&pp[3 * H_ + u0]);
            }
            float cn = sigf(gf) * c_reg + sigf(gi) * tanhf(gg);
            float hn = sigf(go) * tanhf(cn);
            c_reg = cn;
            g_h[b0 * H_ + u0] = hn;
            g_inp[b0 * KIN_ + IN_ + H_ + u0] = hn;
            g_hist[((size_t)b0 * T_ + t) * H_ + u0] = hn;
        }
        gbar(ep);
    }
}

// ---------------------------------------------------------------------------
extern "C" void kernel_launch(void* const* d_in, const int* in_sizes, int n_in,
                              void* d_out, int out_size)
{
    const float* x   = (const float*)d_in[0];
    const float* enc = (const float*)d_in[1];
    const float* Wq  = (const float*)d_in[2];
    const float* Wk  = (const float*)d_in[3];
    const float* v   = (const float*)d_in[4];
    const float* Wih = (const float*)d_in[5];
    const float* Whh = (const float*)d_in[6];
    const float* bih = (const float*)d_in[7];
    const float* bhh = (const float*)d_in[8];
    const float* Wfc = (const float*)d_in[9];
    const float* bfc = (const float*)d_in[10];

    float* keys_p = nullptr;
    float* hist_p = nullptr;
    cudaGetSymbolAddress((void**)&keys_p, g_keys);
    cudaGetSymbolAddress((void**)&hist_p, g_hist);

    dim3 thr(256);

    reset_kernel<<<1, 32>>>();
    pack_kernel<<<512, thr>>>(Wih, Whh, bih, bhh);

    // keys[b,e,a] = enc[b,e,:] . W_key[a,:]
    gemm_abt_kernel<<<dim3((B_ * TE_) / 64, A_ / 64), thr>>>(
        enc, Wk, keys_p, A_, H_, nullptr);
    transpose_kernel<<<dim3(TE_ / 32, A_ / 32, B_), dim3(32, 8)>>>();

    persist_kernel<<<GRID_, thr>>>(x, enc, Wq, v);

    // out[b,t,:] = h_hist[b,t,:] @ Wfc^T + bfc
    gemm_abt_kernel<<<dim3((B_ * T_) / 64, OUT_ / 64), thr>>>(
        hist_p, Wfc, (float*)d_out, OUT_, H_, bfc);
}